// round 7
// baseline (speedup 1.0000x reference)
#include <cuda_runtime.h>
#include <cuda_bf16.h>
#include <math.h>

// ---------------- problem constants ----------------
#define DEPTH   2
#define DIM     512
#define HEADS   8
#define DH      64
#define SEGLEN  512
#define PMEM    4
#define VOCAB   32000
#define BATCH   2
#define SEQ     4096
#define HD      512            // HEADS*DH
#define FFI     1365           // FF_INNER
#define FF2     2730           // 2*FF_INNER
#define FF2P    2816           // FF2 padded to multiple of 128
#define FFIP    1376           // FFI padded to multiple of 32 (K dim)
#define ROWS    (BATCH*SEQ)    // 8192
#define NSEG    (SEQ/SEGLEN)   // 8

// ---------------- scratch (no cudaMalloc allowed) ----------------
__device__ __align__(16) float g_x    [ROWS*DIM];
__device__ __align__(16) float g_xn   [ROWS*DIM];
__device__ __align__(16) float g_qkv  [ROWS*3*HD];
__device__ __align__(16) float g_v    [ROWS*HD];
__device__ __align__(16) float g_vres [ROWS*HD];
__device__ __align__(16) float g_o    [ROWS*HD];
__device__ __align__(16) float g_h    [(size_t)ROWS*FF2P];
__device__ __align__(16) float g_hact [(size_t)ROWS*FFIP];
__device__ __align__(16) float g_mix  [ROWS*HEADS];
__device__ __align__(16) float g_w1pad[DIM*FF2P];
__device__ __align__(16) float g_w2pad[FFIP*DIM];
__device__ __align__(16) float g_wq   [DIM*3*HD];
__device__ __align__(16) float g_wo   [HD*DIM];
__device__ __align__(16) float g_wlog [DIM*VOCAB];

// ---------------- tf32 helpers ----------------
__device__ __forceinline__ float f2tf32(float x) {
    unsigned r;
    asm("cvt.rna.tf32.f32 %0, %1;" : "=r"(r) : "f"(x));
    return __uint_as_float(r);
}

__device__ __forceinline__ void mma8(float* d, const float* a, const float* b) {
    asm volatile(
        "mma.sync.aligned.m16n8k8.row.col.f32.tf32.tf32.f32 "
        "{%0,%1,%2,%3},{%4,%5,%6,%7},{%8,%9},{%0,%1,%2,%3};"
        : "+f"(d[0]), "+f"(d[1]), "+f"(d[2]), "+f"(d[3])
        : "r"(__float_as_uint(a[0])), "r"(__float_as_uint(a[1])),
          "r"(__float_as_uint(a[2])), "r"(__float_as_uint(a[3])),
          "r"(__float_as_uint(b[0])), "r"(__float_as_uint(b[1])));
}

// ---------------- TF32 tensor-core GEMM, 128x128 CTA, 4 warps 64x64 --------
// C[M,N] = A[M,K] @ B[K,N] (+bias[N]) (+add[M,N])
// Requirements: M % 128 == 0, N % 128 == 0, K % 32 == 0.
// A and B must be PRE-ROUNDED to tf32 (rna) in gmem.
#define AS_ST 36     // A smem row stride (frag banks 4g+tg distinct)
#define BS_ST 136    // B smem row stride (frag banks 8tg+g distinct)
#define A_STAGE (128*AS_ST)          // 4608 floats
#define B_STAGE (32*BS_ST)           // 4352 floats
#define STAGEF  (A_STAGE + B_STAGE)  // 8960 floats
#define GEMM_SMEM (3*STAGEF*4)       // 107520 bytes

__device__ __forceinline__ void cpasync16(float* dst_smem, const float* src) {
    unsigned d = (unsigned)__cvta_generic_to_shared(dst_smem);
    asm volatile("cp.async.cg.shared.global [%0], [%1], 16;\n"
                 :: "r"(d), "l"(src));
}

__global__ void __launch_bounds__(128, 2)
gemm_tf32_kernel(const float* __restrict__ A, const float* __restrict__ B,
                 const float* __restrict__ bias, const float* __restrict__ add,
                 float* __restrict__ C, int M, int N, int K) {
    extern __shared__ float sm[];
    const int tid  = threadIdx.x;        // 128 threads, 4 warps
    const int bm   = blockIdx.y * 128;
    const int bn   = blockIdx.x * 128;

    const int lane = tid & 31;
    const int g    = lane >> 2;
    const int tg   = lane & 3;
    const int wid  = tid >> 5;
    const int wm   = (wid & 1) * 64;     // 2x2 warp grid, 64x64 each
    const int wn   = (wid >> 1) * 64;

    float acc[4][8][4];
    #pragma unroll
    for (int mt = 0; mt < 4; mt++)
        #pragma unroll
        for (int nt = 0; nt < 8; nt++)
            #pragma unroll
            for (int c = 0; c < 4; c++) acc[mt][nt][c] = 0.f;

    // staging: A 128x32 (8 f4/thread: one full row), B 32x128 (8 f4/thread)
    const int brr = tid >> 2, bcc = tid & 3;
    const int ntile = K >> 5;

    #define STAGE(t, s) do {                                                  \
        float* as_ = sm + (s) * STAGEF;                                       \
        float* bs_ = as_ + A_STAGE;                                           \
        const float* Ar_ = A + (size_t)(bm + tid) * K + (t) * 32;             \
        _Pragma("unroll")                                                     \
        for (int i_ = 0; i_ < 8; i_++)                                        \
            cpasync16(as_ + tid * AS_ST + i_ * 4, Ar_ + i_ * 4);              \
        const float* Br_ = B + (size_t)((t) * 32 + brr) * N + bn;             \
        _Pragma("unroll")                                                     \
        for (int i_ = 0; i_ < 8; i_++)                                        \
            cpasync16(bs_ + brr * BS_ST + (bcc + i_ * 4) * 4,                 \
                      Br_ + (bcc + i_ * 4) * 4);                              \
        asm volatile("cp.async.commit_group;\n" ::: "memory");                \
    } while (0)

    STAGE(0, 0);
    if (ntile > 1) STAGE(1, 1);
    asm volatile("cp.async.wait_group 1;\n" ::: "memory");
    __syncthreads();

    for (int t = 0; t < ntile; t++) {
        const int s = t % 3;
        if (t + 2 < ntile) STAGE(t + 2, (t + 2) % 3);

        const float* as_ = sm + s * STAGEF;
        const float* bs_ = as_ + A_STAGE;

        #pragma unroll
        for (int ks = 0; ks < 4; ks++) {
            int k0 = ks * 8;
            float af[4][4];
            #pragma unroll
            for (int mt = 0; mt < 4; mt++) {
                int m = wm + mt * 16;
                af[mt][0] = as_[(m + g    ) * AS_ST + k0 + tg    ];
                af[mt][1] = as_[(m + g + 8) * AS_ST + k0 + tg    ];
                af[mt][2] = as_[(m + g    ) * AS_ST + k0 + tg + 4];
                af[mt][3] = as_[(m + g + 8) * AS_ST + k0 + tg + 4];
            }
            float bf[8][2];
            #pragma unroll
            for (int nt = 0; nt < 8; nt++) {
                bf[nt][0] = bs_[(k0 + tg    ) * BS_ST + wn + nt * 8 + g];
                bf[nt][1] = bs_[(k0 + tg + 4) * BS_ST + wn + nt * 8 + g];
            }
            #pragma unroll
            for (int mt = 0; mt < 4; mt++)
                #pragma unroll
                for (int nt = 0; nt < 8; nt++)
                    mma8(acc[mt][nt], af[mt], bf[nt]);
        }

        if (t + 2 < ntile)
            asm volatile("cp.async.wait_group 1;\n" ::: "memory");
        else
            asm volatile("cp.async.wait_group 0;\n" ::: "memory");
        __syncthreads();
    }

    // epilogue
    #pragma unroll
    for (int mt = 0; mt < 4; mt++) {
        #pragma unroll
        for (int nt = 0; nt < 8; nt++) {
            int r0 = bm + wm + mt * 16 + g;
            int c0 = bn + wn + nt * 8 + tg * 2;
            #pragma unroll
            for (int half = 0; half < 2; half++) {
                int r = r0 + half * 8;
                float v0 = acc[mt][nt][half * 2 + 0];
                float v1 = acc[mt][nt][half * 2 + 1];
                if (bias) { v0 += bias[c0]; v1 += bias[c0 + 1]; }
                if (add)  { v0 += add[(size_t)r * N + c0];
                            v1 += add[(size_t)r * N + c0 + 1]; }
                C[(size_t)r * N + c0]     = v0;
                C[(size_t)r * N + c0 + 1] = v1;
            }
        }
    }
}

static inline void launch_gemm(const float* A, const float* B, const float* bias,
                               const float* add, float* C, int M, int N, int K) {
    dim3 grid(N / 128, M / 128);
    gemm_tf32_kernel<<<grid, 128, GEMM_SMEM>>>(A, B, bias, add, C, M, N, K);
}

// ---------------- rna round-copy (for weight B operands) ----------------
__global__ void roundcopy_kernel(const float* __restrict__ in,
                                 float* __restrict__ out, int n4) {
    int i = blockIdx.x * blockDim.x + threadIdx.x;
    if (i >= n4) return;
    float4 v = ((const float4*)in)[i];
    ((float4*)out)[i] = make_float4(f2tf32(v.x), f2tf32(v.y),
                                    f2tf32(v.z), f2tf32(v.w));
}

// ---------------- embedding ----------------
__global__ void embed_kernel(const int* __restrict__ tokens,
                             const float* __restrict__ tok_emb,
                             const float* __restrict__ pos_emb,
                             float* __restrict__ x) {
    int row = blockIdx.x;
    int s = row % SEQ;
    int tok = tokens[row];
    const float* te = tok_emb + (size_t)tok * DIM;
    const float* pe = pos_emb + (size_t)s * DIM;
    float* xr = x + (size_t)row * DIM;
    for (int c = threadIdx.x; c < DIM; c += blockDim.x)
        xr[c] = te[c] + pe[c];
}

// ---------------- rmsnorm (tf32-rounded output: GEMM A operand) ------------
__global__ void rmsnorm_kernel(const float* __restrict__ in,
                               const float* __restrict__ w,
                               float* __restrict__ out) {
    int row = blockIdx.x;
    const float* xr = in + (size_t)row * DIM;
    float* orow = out + (size_t)row * DIM;
    int tid = threadIdx.x; // 128
    float acc = 0.f;
    float v[4];
    #pragma unroll
    for (int i = 0; i < 4; i++) {
        v[i] = xr[tid + i * 128];
        acc += v[i] * v[i];
    }
    for (int off = 16; off; off >>= 1) acc += __shfl_down_sync(~0u, acc, off);
    __shared__ float sh[4];
    int lane = tid & 31, wp = tid >> 5;
    if (lane == 0) sh[wp] = acc;
    __syncthreads();
    __shared__ float s_scale;
    if (tid == 0) {
        float ss = (sh[0] + sh[1] + sh[2] + sh[3]) / (float)DIM;
        s_scale = rsqrtf(ss + 1e-6f);
    }
    __syncthreads();
    float sc = s_scale;
    #pragma unroll
    for (int i = 0; i < 4; i++) {
        int c = tid + i * 128;
        orow[c] = f2tf32(v[i] * sc * w[c]);
    }
}

// ---------------- vmix ----------------
__global__ void vmix_kernel(const float* __restrict__ xn,
                            const float* __restrict__ w,   // [512,8]
                            const float* __restrict__ b,   // [8]
                            float* __restrict__ mix) {
    int row = blockIdx.x, tid = threadIdx.x; // 128
    float acc[8] = {0,0,0,0,0,0,0,0};
    const float* xr = xn + (size_t)row * DIM;
    for (int k = tid; k < DIM; k += 128) {
        float xv = xr[k];
        const float* wr = w + k * HEADS;
        #pragma unroll
        for (int h = 0; h < 8; h++) acc[h] += xv * wr[h];
    }
    __shared__ float sh[4][8];
    int lane = tid & 31, wp = tid >> 5;
    #pragma unroll
    for (int h = 0; h < 8; h++) {
        float v = acc[h];
        for (int off = 16; off; off >>= 1) v += __shfl_down_sync(~0u, v, off);
        if (lane == 0) sh[wp][h] = v;
    }
    __syncthreads();
    if (tid < 8) {
        float v = sh[0][tid] + sh[1][tid] + sh[2][tid] + sh[3][tid] + b[tid];
        mix[(size_t)row * HEADS + tid] = 1.f / (1.f + expf(-v));
    }
}

// ---------------- v preparation ----------------
__global__ void vprep_kernel(const float* __restrict__ qkv,
                             const float* __restrict__ mix,
                             const float* __restrict__ vres,
                             float* __restrict__ vout,
                             float* __restrict__ vres_out) {
    size_t idx = (size_t)blockIdx.x * blockDim.x + threadIdx.x;
    if (idx >= (size_t)ROWS * HD) return;
    size_t row = idx >> 9;
    int col = (int)(idx & 511);
    int h = col >> 6;
    float v = qkv[row * (3 * HD) + 2 * HD + col];
    if (vres_out) vres_out[idx] = v;
    if (mix) {
        float mx = mix[row * HEADS + h];
        v = v + (vres[idx] - v) * mx;
    }
    vout[idx] = v;
}

// ---------------- rope ----------------
__global__ void rope_kernel(float* __restrict__ qkv) {
    size_t idx = (size_t)blockIdx.x * blockDim.x + threadIdx.x;
    if (idx >= (size_t)ROWS * 2 * HEADS * 32) return;
    int i  = (int)(idx & 31);
    int h  = (int)((idx >> 5) & 7);
    int qk = (int)((idx >> 8) & 1);
    size_t row = idx >> 9;
    int s = (int)(row % SEQ);
    double e = (double)(2 * i) / 64.0;
    float inv = (float)pow(10000.0, -e);
    float f = (float)s * inv;
    float cs, sn;
    sincosf(f, &sn, &cs);
    size_t base = row * (3 * HD) + (size_t)qk * HD + h * DH + 2 * i;
    float x1 = qkv[base], x2 = qkv[base + 1];
    qkv[base]     = x1 * cs - x2 * sn;
    qkv[base + 1] = x1 * sn + x2 * cs;
}

// ---------------- attention (tf32-rounded output: GEMM A operand) ----------
__global__ void __launch_bounds__(128)
attn_kernel(const float* __restrict__ qkv,
            const float* __restrict__ vmem,
            const float* __restrict__ pmem,
            float* __restrict__ out) {
    const int qb = blockIdx.x, w = blockIdx.y;
    const int b = blockIdx.z / HEADS, h = blockIdx.z % HEADS;
    const int tid = threadIdx.x;
    const int qi = qb * 128 + tid;
    const int s = w * SEGLEN + qi;
    const size_t row = (size_t)(b * SEQ + s);

    float q[64];
    {
        const float* qp = qkv + row * (3 * HD) + h * DH;
        #pragma unroll
        for (int c = 0; c < 64; c++) q[c] = qp[c] * 0.125f;
    }
    float o[64];
    #pragma unroll
    for (int c = 0; c < 64; c++) o[c] = 0.f;
    float m = -INFINITY, l = 0.f;

    __shared__ float ks[32][64];
    __shared__ float vs[32][64];

    const int jmax = qi + PMEM;
    const int qi_last = qb * 128 + 127;
    const int nch = (qi_last + PMEM) / 32 + 1;

    for (int ch = 0; ch < nch; ch++) {
        const int j0 = ch * 32;
        for (int e = tid; e < 32 * 64; e += 128) {
            int jj = e >> 6, c = e & 63;
            int j = j0 + jj;
            float kv = 0.f, vv = 0.f;
            if (j < PMEM) {
                kv = pmem[(0 * HEADS + h) * PMEM * DH + j * DH + c];
                vv = pmem[(1 * HEADS + h) * PMEM * DH + j * DH + c];
            } else if (j - PMEM < SEGLEN) {
                int sk = w * SEGLEN + (j - PMEM);
                size_t rk = (size_t)(b * SEQ + sk);
                kv = qkv[rk * (3 * HD) + HD + h * DH + c];
                vv = vmem[rk * HD + h * DH + c];
            }
            ks[jj][c] = kv;
            vs[jj][c] = vv;
        }
        __syncthreads();

        if (j0 <= jmax) {
            float sc[32];
            float cmax = -INFINITY;
            #pragma unroll
            for (int jj = 0; jj < 32; jj++) {
                float acc = 0.f;
                #pragma unroll
                for (int c = 0; c < 64; c += 4) {
                    float4 k4 = *(const float4*)&ks[jj][c];
                    acc += q[c] * k4.x + q[c+1] * k4.y + q[c+2] * k4.z + q[c+3] * k4.w;
                }
                sc[jj] = (j0 + jj <= jmax) ? acc : -INFINITY;
                cmax = fmaxf(cmax, sc[jj]);
            }
            float mnew = fmaxf(m, cmax);
            float f = __expf(m - mnew);
            l *= f;
            #pragma unroll
            for (int c = 0; c < 64; c++) o[c] *= f;
            #pragma unroll
            for (int jj = 0; jj < 32; jj++) {
                float p = __expf(sc[jj] - mnew);
                l += p;
                #pragma unroll
                for (int c = 0; c < 64; c += 4) {
                    float4 v4 = *(const float4*)&vs[jj][c];
                    o[c]   += p * v4.x;
                    o[c+1] += p * v4.y;
                    o[c+2] += p * v4.z;
                    o[c+3] += p * v4.w;
                }
            }
            m = mnew;
        }
        __syncthreads();
    }

    float invl = 1.f / l;
    float* op = out + row * HD + h * DH;
    #pragma unroll
    for (int c = 0; c < 64; c++) op[c] = f2tf32(o[c] * invl);
}

// ---------------- GEGLU (adds ff1 bias; tf32-rounded output) ----------------
__global__ void geglu_kernel(const float* __restrict__ h,     // [ROWS, FF2P]
                             const float* __restrict__ b1,    // [FF2]
                             float* __restrict__ hact) {      // [ROWS, FFIP]
    size_t idx = (size_t)blockIdx.x * blockDim.x + threadIdx.x;
    if (idx >= (size_t)ROWS * FFIP) return;
    size_t row = idx / FFIP;
    int i = (int)(idx - row * FFIP);
    float val = 0.f;
    if (i < FFI) {
        float a  = h[row * FF2P + i]       + b1[i];
        float gg = h[row * FF2P + FFI + i] + b1[FFI + i];
        float sig = 1.f / (1.f + expf(-gg));
        val = f2tf32(a * gg * sig);
    }
    hact[idx] = val;
}

// ---------------- ff_w1 pad+round: [DIM, FF2] -> [DIM, FF2P] ----------------
__global__ void padw1_kernel(const float* __restrict__ w,
                             float* __restrict__ out) {
    int idx = blockIdx.x * blockDim.x + threadIdx.x;
    if (idx >= DIM * FF2P) return;
    int r = idx / FF2P, c = idx - r * FF2P;
    out[idx] = (c < FF2) ? f2tf32(w[(size_t)r * FF2 + c]) : 0.f;
}

// ---------------- ff_w2 pad+round: [FFI, DIM] -> [FFIP, DIM] ----------------
__global__ void padw2_kernel(const float* __restrict__ w,
                             float* __restrict__ out) {
    int idx = blockIdx.x * blockDim.x + threadIdx.x;
    if (idx >= FFIP * DIM) return;
    int k = idx / DIM;
    out[idx] = (k < FFI) ? f2tf32(w[idx]) : 0.f;
}

// ---------------- launch ----------------
extern "C" void kernel_launch(void* const* d_in, const int* in_sizes, int n_in,
                              void* d_out, int out_size) {
    const int*   tokens       = (const int*)  d_in[0];
    const float* tok_emb      = (const float*)d_in[1];
    const float* pos_emb      = (const float*)d_in[2];
    const float* attn_norm_w  = (const float*)d_in[3];
    const float* Wqkv         = (const float*)d_in[4];
    const float* persist_mem  = (const float*)d_in[5];
    const float* Wout         = (const float*)d_in[6];
    const float* vmix_w       = (const float*)d_in[7];
    const float* vmix_b       = (const float*)d_in[8];
    const float* ff_norm_w    = (const float*)d_in[9];
    const float* ff_w1        = (const float*)d_in[10];
    const float* ff_b1        = (const float*)d_in[11];
    const float* ff_w2        = (const float*)d_in[12];
    const float* ff_b2        = (const float*)d_in[13];
    const float* final_norm_w = (const float*)d_in[14];
    const float* w_logits     = (const float*)d_in[15];
    float* out = (float*)d_out;

    float *x, *xn, *qkv, *v, *vres, *o, *hbuf, *hact, *mix;
    float *w1pad, *w2pad, *wq, *wo, *wlog;
    cudaGetSymbolAddress((void**)&x,     g_x);
    cudaGetSymbolAddress((void**)&xn,    g_xn);
    cudaGetSymbolAddress((void**)&qkv,   g_qkv);
    cudaGetSymbolAddress((void**)&v,     g_v);
    cudaGetSymbolAddress((void**)&vres,  g_vres);
    cudaGetSymbolAddress((void**)&o,     g_o);
    cudaGetSymbolAddress((void**)&hbuf,  g_h);
    cudaGetSymbolAddress((void**)&hact,  g_hact);
    cudaGetSymbolAddress((void**)&mix,   g_mix);
    cudaGetSymbolAddress((void**)&w1pad, g_w1pad);
    cudaGetSymbolAddress((void**)&w2pad, g_w2pad);
    cudaGetSymbolAddress((void**)&wq,    g_wq);
    cudaGetSymbolAddress((void**)&wo,    g_wo);
    cudaGetSymbolAddress((void**)&wlog,  g_wlog);

    cudaFuncSetAttribute(gemm_tf32_kernel,
                         cudaFuncAttributeMaxDynamicSharedMemorySize, GEMM_SMEM);

    embed_kernel<<<ROWS, 256>>>(tokens, tok_emb, pos_emb, x);

    // pre-round the big logits weight once per launch
    roundcopy_kernel<<<(DIM * VOCAB / 4 + 255) / 256, 256>>>(w_logits, wlog,
                                                             DIM * VOCAB / 4);

    for (int d = 0; d < DEPTH; d++) {
        rmsnorm_kernel<<<ROWS, 128>>>(x, attn_norm_w + d * DIM, xn);
        roundcopy_kernel<<<(DIM * 3 * HD / 4 + 255) / 256, 256>>>(
            Wqkv + (size_t)d * DIM * 3 * HD, wq, DIM * 3 * HD / 4);
        launch_gemm(xn, wq, nullptr, nullptr, qkv, ROWS, 3 * HD, DIM);
        if (d > 0)
            vmix_kernel<<<ROWS, 128>>>(xn, vmix_w + (size_t)d * DIM * HEADS,
                                       vmix_b + d * HEADS, mix);
        {
            size_t n = (size_t)ROWS * HD;
            vprep_kernel<<<(unsigned)((n + 255) / 256), 256>>>(
                qkv, d > 0 ? mix : nullptr, vres, v, d == 0 ? vres : nullptr);
        }
        {
            size_t n = (size_t)ROWS * 2 * HEADS * 32;
            rope_kernel<<<(unsigned)((n + 255) / 256), 256>>>(qkv);
        }
        attn_kernel<<<dim3(4, NSEG, BATCH * HEADS), 128>>>(
            qkv, v, persist_mem + (size_t)d * 2 * HEADS * PMEM * DH, o);
        roundcopy_kernel<<<(HD * DIM / 4 + 255) / 256, 256>>>(
            Wout + (size_t)d * HD * DIM, wo, HD * DIM / 4);
        launch_gemm(o, wo, nullptr, x, x, ROWS, DIM, HD);
        rmsnorm_kernel<<<ROWS, 128>>>(x, ff_norm_w + d * DIM, xn);
        padw1_kernel<<<(DIM * FF2P + 255) / 256, 256>>>(
            ff_w1 + (size_t)d * DIM * FF2, w1pad);
        launch_gemm(xn, w1pad, nullptr, nullptr, hbuf, ROWS, FF2P, DIM);
        {
            size_t n = (size_t)ROWS * FFIP;
            geglu_kernel<<<(unsigned)((n + 255) / 256), 256>>>(
                hbuf, ff_b1 + (size_t)d * FF2, hact);
        }
        padw2_kernel<<<(FFIP * DIM + 255) / 256, 256>>>(
            ff_w2 + (size_t)d * FFI * DIM, w2pad);
        launch_gemm(hact, w2pad, ff_b2 + (size_t)d * DIM, x, x,
                    ROWS, DIM, FFIP);
    }

    rmsnorm_kernel<<<ROWS, 128>>>(x, final_norm_w, xn);
    launch_gemm(xn, wlog, nullptr, nullptr, out, ROWS, VOCAB, DIM);
}

// round 8
// speedup vs baseline: 1.5786x; 1.5786x over previous
#include <cuda_runtime.h>
#include <cuda_bf16.h>
#include <math.h>

// ---------------- problem constants ----------------
#define DEPTH   2
#define DIM     512
#define HEADS   8
#define DH      64
#define SEGLEN  512
#define PMEM    4
#define VOCAB   32000
#define BATCH   2
#define SEQ     4096
#define HD      512            // HEADS*DH
#define FFI     1365           // FF_INNER
#define FF2     2730           // 2*FF_INNER
#define FF2P    2816           // FF2 padded to multiple of 128
#define FFIP    1376           // FFI padded to multiple of 32 (K dim)
#define ROWS    (BATCH*SEQ)    // 8192
#define NSEG    (SEQ/SEGLEN)   // 8

// ---------------- scratch (no cudaMalloc allowed) ----------------
__device__ __align__(16) float g_x    [ROWS*DIM];
__device__ __align__(16) float g_xn   [ROWS*DIM];
__device__ __align__(16) float g_qkv  [ROWS*3*HD];
__device__ __align__(16) float g_v    [ROWS*HD];
__device__ __align__(16) float g_vres [ROWS*HD];
__device__ __align__(16) float g_o    [ROWS*HD];
__device__ __align__(16) float g_h    [(size_t)ROWS*FF2P];
__device__ __align__(16) float g_hact [(size_t)ROWS*FFIP];
__device__ __align__(16) float g_mix  [ROWS*HEADS];
__device__ __align__(16) float g_w1pad[DIM*FF2P];
__device__ __align__(16) float g_w2pad[FFIP*DIM];
__device__ __align__(16) float g_wq   [DIM*3*HD];
__device__ __align__(16) float g_wo   [HD*DIM];
__device__ __align__(16) float g_wlog [DIM*VOCAB];

// ---------------- tf32 helpers ----------------
__device__ __forceinline__ float f2tf32(float x) {
    unsigned r;
    asm("cvt.rna.tf32.f32 %0, %1;" : "=r"(r) : "f"(x));
    return __uint_as_float(r);
}

__device__ __forceinline__ void mma8(float* d, const float* a, const float* b) {
    asm volatile(
        "mma.sync.aligned.m16n8k8.row.col.f32.tf32.tf32.f32 "
        "{%0,%1,%2,%3},{%4,%5,%6,%7},{%8,%9},{%0,%1,%2,%3};"
        : "+f"(d[0]), "+f"(d[1]), "+f"(d[2]), "+f"(d[3])
        : "r"(__float_as_uint(a[0])), "r"(__float_as_uint(a[1])),
          "r"(__float_as_uint(a[2])), "r"(__float_as_uint(a[3])),
          "r"(__float_as_uint(b[0])), "r"(__float_as_uint(b[1])));
}

// ---------------- TF32 tensor-core GEMM, cp.async 3-stage (R4 config) ------
// C[M,N] = A[M,K] @ B[K,N] (+bias[N]) (+add[M,N])
// Requirements: M % 128 == 0, N % 128 == 0, K % 32 == 0.
// A and B must be PRE-ROUNDED to tf32 (rna) in gmem.
#define AS_ST 36     // A smem row stride (frag banks 4g+tg distinct)
#define BS_ST 136    // B smem row stride (frag banks 8tg+g distinct)
#define A_STAGE (128*AS_ST)          // 4608 floats
#define B_STAGE (32*BS_ST)           // 4352 floats
#define STAGEF  (A_STAGE + B_STAGE)  // 8960 floats
#define GEMM_SMEM (3*STAGEF*4)       // 107520 bytes

__device__ __forceinline__ void cpasync16(float* dst_smem, const float* src) {
    unsigned d = (unsigned)__cvta_generic_to_shared(dst_smem);
    asm volatile("cp.async.cg.shared.global [%0], [%1], 16;\n"
                 :: "r"(d), "l"(src));
}

__global__ void __launch_bounds__(256, 2)
gemm_tf32_kernel(const float* __restrict__ A, const float* __restrict__ B,
                 const float* __restrict__ bias, const float* __restrict__ add,
                 float* __restrict__ C, int M, int N, int K) {
    extern __shared__ float sm[];
    const int tid  = threadIdx.x;
    const int bm   = blockIdx.y * 128;
    const int bn   = blockIdx.x * 128;

    const int lane = tid & 31;
    const int g    = lane >> 2;
    const int tg   = lane & 3;
    const int wid  = tid >> 5;
    const int wm   = (wid & 3) * 32;
    const int wn   = (wid >> 2) * 64;

    float acc[2][8][4];
    #pragma unroll
    for (int mt = 0; mt < 2; mt++)
        #pragma unroll
        for (int nt = 0; nt < 8; nt++)
            #pragma unroll
            for (int c = 0; c < 4; c++) acc[mt][nt][c] = 0.f;

    const int ntile = K >> 5;

    #define STAGE(t, s) do {                                                  \
        float* as_ = sm + (s) * STAGEF;                                       \
        float* bs_ = as_ + A_STAGE;                                           \
        _Pragma("unroll")                                                     \
        for (int i_ = 0; i_ < 4; i_++) {                                      \
            int lin = tid + i_ * 256;                                         \
            int r = lin >> 3, c = (lin & 7) * 4;                              \
            cpasync16(as_ + r * AS_ST + c,                                    \
                      A + (size_t)(bm + r) * K + (t) * 32 + c);               \
        }                                                                     \
        _Pragma("unroll")                                                     \
        for (int i_ = 0; i_ < 4; i_++) {                                      \
            int lin = tid + i_ * 256;                                         \
            int r = lin >> 5, c = (lin & 31) * 4;                             \
            cpasync16(bs_ + r * BS_ST + c,                                    \
                      B + (size_t)((t) * 32 + r) * N + bn + c);               \
        }                                                                     \
        asm volatile("cp.async.commit_group;\n" ::: "memory");                \
    } while (0)

    STAGE(0, 0);
    if (ntile > 1) STAGE(1, 1);
    asm volatile("cp.async.wait_group 1;\n" ::: "memory");
    __syncthreads();

    for (int t = 0; t < ntile; t++) {
        const int s = t % 3;
        if (t + 2 < ntile) STAGE(t + 2, (t + 2) % 3);

        const float* as_ = sm + s * STAGEF;
        const float* bs_ = as_ + A_STAGE;

        #pragma unroll
        for (int ks = 0; ks < 4; ks++) {
            int k0 = ks * 8;
            float af[2][4];
            #pragma unroll
            for (int mt = 0; mt < 2; mt++) {
                int m = wm + mt * 16;
                af[mt][0] = as_[(m + g    ) * AS_ST + k0 + tg    ];
                af[mt][1] = as_[(m + g + 8) * AS_ST + k0 + tg    ];
                af[mt][2] = as_[(m + g    ) * AS_ST + k0 + tg + 4];
                af[mt][3] = as_[(m + g + 8) * AS_ST + k0 + tg + 4];
            }
            float bf[8][2];
            #pragma unroll
            for (int nt = 0; nt < 8; nt++) {
                bf[nt][0] = bs_[(k0 + tg    ) * BS_ST + wn + nt * 8 + g];
                bf[nt][1] = bs_[(k0 + tg + 4) * BS_ST + wn + nt * 8 + g];
            }
            #pragma unroll
            for (int mt = 0; mt < 2; mt++)
                #pragma unroll
                for (int nt = 0; nt < 8; nt++)
                    mma8(acc[mt][nt], af[mt], bf[nt]);
        }

        if (t + 2 < ntile)
            asm volatile("cp.async.wait_group 1;\n" ::: "memory");
        else
            asm volatile("cp.async.wait_group 0;\n" ::: "memory");
        __syncthreads();
    }

    // epilogue
    #pragma unroll
    for (int mt = 0; mt < 2; mt++) {
        #pragma unroll
        for (int nt = 0; nt < 8; nt++) {
            int r0 = bm + wm + mt * 16 + g;
            int c0 = bn + wn + nt * 8 + tg * 2;
            #pragma unroll
            for (int half = 0; half < 2; half++) {
                int r = r0 + half * 8;
                float v0 = acc[mt][nt][half * 2 + 0];
                float v1 = acc[mt][nt][half * 2 + 1];
                if (bias) { v0 += bias[c0]; v1 += bias[c0 + 1]; }
                if (add)  { v0 += add[(size_t)r * N + c0];
                            v1 += add[(size_t)r * N + c0 + 1]; }
                C[(size_t)r * N + c0]     = v0;
                C[(size_t)r * N + c0 + 1] = v1;
            }
        }
    }
}

static inline void launch_gemm(const float* A, const float* B, const float* bias,
                               const float* add, float* C, int M, int N, int K) {
    dim3 grid(N / 128, M / 128);
    gemm_tf32_kernel<<<grid, 256, GEMM_SMEM>>>(A, B, bias, add, C, M, N, K);
}

// ---------------- rna round-copy (for weight B operands) ----------------
__global__ void roundcopy_kernel(const float* __restrict__ in,
                                 float* __restrict__ out, int n4) {
    int i = blockIdx.x * blockDim.x + threadIdx.x;
    if (i >= n4) return;
    float4 v = ((const float4*)in)[i];
    ((float4*)out)[i] = make_float4(f2tf32(v.x), f2tf32(v.y),
                                    f2tf32(v.z), f2tf32(v.w));
}

// ---------------- embedding ----------------
__global__ void embed_kernel(const int* __restrict__ tokens,
                             const float* __restrict__ tok_emb,
                             const float* __restrict__ pos_emb,
                             float* __restrict__ x) {
    int row = blockIdx.x;
    int s = row % SEQ;
    int tok = tokens[row];
    const float* te = tok_emb + (size_t)tok * DIM;
    const float* pe = pos_emb + (size_t)s * DIM;
    float* xr = x + (size_t)row * DIM;
    for (int c = threadIdx.x; c < DIM; c += blockDim.x)
        xr[c] = te[c] + pe[c];
}

// ---------------- rmsnorm (tf32-rounded output: GEMM A operand) ------------
__global__ void rmsnorm_kernel(const float* __restrict__ in,
                               const float* __restrict__ w,
                               float* __restrict__ out) {
    int row = blockIdx.x;
    const float* xr = in + (size_t)row * DIM;
    float* orow = out + (size_t)row * DIM;
    int tid = threadIdx.x; // 128
    float acc = 0.f;
    float v[4];
    #pragma unroll
    for (int i = 0; i < 4; i++) {
        v[i] = xr[tid + i * 128];
        acc += v[i] * v[i];
    }
    for (int off = 16; off; off >>= 1) acc += __shfl_down_sync(~0u, acc, off);
    __shared__ float sh[4];
    int lane = tid & 31, wp = tid >> 5;
    if (lane == 0) sh[wp] = acc;
    __syncthreads();
    __shared__ float s_scale;
    if (tid == 0) {
        float ss = (sh[0] + sh[1] + sh[2] + sh[3]) / (float)DIM;
        s_scale = rsqrtf(ss + 1e-6f);
    }
    __syncthreads();
    float sc = s_scale;
    #pragma unroll
    for (int i = 0; i < 4; i++) {
        int c = tid + i * 128;
        orow[c] = f2tf32(v[i] * sc * w[c]);
    }
}

// ---------------- vmix ----------------
__global__ void vmix_kernel(const float* __restrict__ xn,
                            const float* __restrict__ w,   // [512,8]
                            const float* __restrict__ b,   // [8]
                            float* __restrict__ mix) {
    int row = blockIdx.x, tid = threadIdx.x; // 128
    float acc[8] = {0,0,0,0,0,0,0,0};
    const float* xr = xn + (size_t)row * DIM;
    for (int k = tid; k < DIM; k += 128) {
        float xv = xr[k];
        const float* wr = w + k * HEADS;
        #pragma unroll
        for (int h = 0; h < 8; h++) acc[h] += xv * wr[h];
    }
    __shared__ float sh[4][8];
    int lane = tid & 31, wp = tid >> 5;
    #pragma unroll
    for (int h = 0; h < 8; h++) {
        float v = acc[h];
        for (int off = 16; off; off >>= 1) v += __shfl_down_sync(~0u, v, off);
        if (lane == 0) sh[wp][h] = v;
    }
    __syncthreads();
    if (tid < 8) {
        float v = sh[0][tid] + sh[1][tid] + sh[2][tid] + sh[3][tid] + b[tid];
        mix[(size_t)row * HEADS + tid] = 1.f / (1.f + expf(-v));
    }
}

// ---------------- v preparation ----------------
__global__ void vprep_kernel(const float* __restrict__ qkv,
                             const float* __restrict__ mix,
                             const float* __restrict__ vres,
                             float* __restrict__ vout,
                             float* __restrict__ vres_out) {
    size_t idx = (size_t)blockIdx.x * blockDim.x + threadIdx.x;
    if (idx >= (size_t)ROWS * HD) return;
    size_t row = idx >> 9;
    int col = (int)(idx & 511);
    int h = col >> 6;
    float v = qkv[row * (3 * HD) + 2 * HD + col];
    if (vres_out) vres_out[idx] = v;
    if (mix) {
        float mx = mix[row * HEADS + h];
        v = v + (vres[idx] - v) * mx;
    }
    vout[idx] = v;
}

// ---------------- rope ----------------
__global__ void rope_kernel(float* __restrict__ qkv) {
    size_t idx = (size_t)blockIdx.x * blockDim.x + threadIdx.x;
    if (idx >= (size_t)ROWS * 2 * HEADS * 32) return;
    int i  = (int)(idx & 31);
    int h  = (int)((idx >> 5) & 7);
    int qk = (int)((idx >> 8) & 1);
    size_t row = idx >> 9;
    int s = (int)(row % SEQ);
    // 10000^(-2i/64) = exp2(-i * log2(10000)/32)
    float inv = exp2f(-(float)i * 0.41524103f);
    float f = (float)s * inv;
    float cs, sn;
    sincosf(f, &sn, &cs);
    size_t base = row * (3 * HD) + (size_t)qk * HD + h * DH + 2 * i;
    float x1 = qkv[base], x2 = qkv[base + 1];
    qkv[base]     = x1 * cs - x2 * sn;
    qkv[base + 1] = x1 * sn + x2 * cs;
}

// ---------------- attention (tf32-rounded output: GEMM A operand) ----------
__global__ void __launch_bounds__(128)
attn_kernel(const float* __restrict__ qkv,
            const float* __restrict__ vmem,
            const float* __restrict__ pmem,
            float* __restrict__ out) {
    const int qb = blockIdx.x, w = blockIdx.y;
    const int b = blockIdx.z / HEADS, h = blockIdx.z % HEADS;
    const int tid = threadIdx.x;
    const int qi = qb * 128 + tid;
    const int s = w * SEGLEN + qi;
    const size_t row = (size_t)(b * SEQ + s);

    float q[64];
    {
        const float* qp = qkv + row * (3 * HD) + h * DH;
        #pragma unroll
        for (int c = 0; c < 64; c++) q[c] = qp[c] * 0.125f;
    }
    float o[64];
    #pragma unroll
    for (int c = 0; c < 64; c++) o[c] = 0.f;
    float m = -INFINITY, l = 0.f;

    __shared__ float ks[32][64];
    __shared__ float vs[32][64];

    const int jmax = qi + PMEM;
    const int qi_last = qb * 128 + 127;
    const int nch = (qi_last + PMEM) / 32 + 1;

    for (int ch = 0; ch < nch; ch++) {
        const int j0 = ch * 32;
        for (int e = tid; e < 32 * 64; e += 128) {
            int jj = e >> 6, c = e & 63;
            int j = j0 + jj;
            float kv = 0.f, vv = 0.f;
            if (j < PMEM) {
                kv = pmem[(0 * HEADS + h) * PMEM * DH + j * DH + c];
                vv = pmem[(1 * HEADS + h) * PMEM * DH + j * DH + c];
            } else if (j - PMEM < SEGLEN) {
                int sk = w * SEGLEN + (j - PMEM);
                size_t rk = (size_t)(b * SEQ + sk);
                kv = qkv[rk * (3 * HD) + HD + h * DH + c];
                vv = vmem[rk * HD + h * DH + c];
            }
            ks[jj][c] = kv;
            vs[jj][c] = vv;
        }
        __syncthreads();

        if (j0 <= jmax) {
            float sc[32];
            float cmax = -INFINITY;
            #pragma unroll
            for (int jj = 0; jj < 32; jj++) {
                float acc = 0.f;
                #pragma unroll
                for (int c = 0; c < 64; c += 4) {
                    float4 k4 = *(const float4*)&ks[jj][c];
                    acc += q[c] * k4.x + q[c+1] * k4.y + q[c+2] * k4.z + q[c+3] * k4.w;
                }
                sc[jj] = (j0 + jj <= jmax) ? acc : -INFINITY;
                cmax = fmaxf(cmax, sc[jj]);
            }
            float mnew = fmaxf(m, cmax);
            float f = __expf(m - mnew);
            l *= f;
            #pragma unroll
            for (int c = 0; c < 64; c++) o[c] *= f;
            #pragma unroll
            for (int jj = 0; jj < 32; jj++) {
                float p = __expf(sc[jj] - mnew);
                l += p;
                #pragma unroll
                for (int c = 0; c < 64; c += 4) {
                    float4 v4 = *(const float4*)&vs[jj][c];
                    o[c]   += p * v4.x;
                    o[c+1] += p * v4.y;
                    o[c+2] += p * v4.z;
                    o[c+3] += p * v4.w;
                }
            }
            m = mnew;
        }
        __syncthreads();
    }

    float invl = 1.f / l;
    float* op = out + row * HD + h * DH;
    #pragma unroll
    for (int c = 0; c < 64; c++) op[c] = f2tf32(o[c] * invl);
}

// ---------------- GEGLU (adds ff1 bias; tf32-rounded output) ----------------
__global__ void geglu_kernel(const float* __restrict__ h,     // [ROWS, FF2P]
                             const float* __restrict__ b1,    // [FF2]
                             float* __restrict__ hact) {      // [ROWS, FFIP]
    size_t idx = (size_t)blockIdx.x * blockDim.x + threadIdx.x;
    if (idx >= (size_t)ROWS * FFIP) return;
    size_t row = idx / FFIP;
    int i = (int)(idx - row * FFIP);
    float val = 0.f;
    if (i < FFI) {
        float a  = h[row * FF2P + i]       + b1[i];
        float gg = h[row * FF2P + FFI + i] + b1[FFI + i];
        float sig = 1.f / (1.f + expf(-gg));
        val = f2tf32(a * gg * sig);
    }
    hact[idx] = val;
}

// ---------------- ff_w1 pad+round: [DIM, FF2] -> [DIM, FF2P] ----------------
__global__ void padw1_kernel(const float* __restrict__ w,
                             float* __restrict__ out) {
    int idx = blockIdx.x * blockDim.x + threadIdx.x;
    if (idx >= DIM * FF2P) return;
    int r = idx / FF2P, c = idx - r * FF2P;
    out[idx] = (c < FF2) ? f2tf32(w[(size_t)r * FF2 + c]) : 0.f;
}

// ---------------- ff_w2 pad+round: [FFI, DIM] -> [FFIP, DIM] ----------------
__global__ void padw2_kernel(const float* __restrict__ w,
                             float* __restrict__ out) {
    int idx = blockIdx.x * blockDim.x + threadIdx.x;
    if (idx >= FFIP * DIM) return;
    int k = idx / DIM;
    out[idx] = (k < FFI) ? f2tf32(w[idx]) : 0.f;
}

// ---------------- launch ----------------
extern "C" void kernel_launch(void* const* d_in, const int* in_sizes, int n_in,
                              void* d_out, int out_size) {
    const int*   tokens       = (const int*)  d_in[0];
    const float* tok_emb      = (const float*)d_in[1];
    const float* pos_emb      = (const float*)d_in[2];
    const float* attn_norm_w  = (const float*)d_in[3];
    const float* Wqkv         = (const float*)d_in[4];
    const float* persist_mem  = (const float*)d_in[5];
    const float* Wout         = (const float*)d_in[6];
    const float* vmix_w       = (const float*)d_in[7];
    const float* vmix_b       = (const float*)d_in[8];
    const float* ff_norm_w    = (const float*)d_in[9];
    const float* ff_w1        = (const float*)d_in[10];
    const float* ff_b1        = (const float*)d_in[11];
    const float* ff_w2        = (const float*)d_in[12];
    const float* ff_b2        = (const float*)d_in[13];
    const float* final_norm_w = (const float*)d_in[14];
    const float* w_logits     = (const float*)d_in[15];
    float* out = (float*)d_out;

    float *x, *xn, *qkv, *v, *vres, *o, *hbuf, *hact, *mix;
    float *w1pad, *w2pad, *wq, *wo, *wlog;
    cudaGetSymbolAddress((void**)&x,     g_x);
    cudaGetSymbolAddress((void**)&xn,    g_xn);
    cudaGetSymbolAddress((void**)&qkv,   g_qkv);
    cudaGetSymbolAddress((void**)&v,     g_v);
    cudaGetSymbolAddress((void**)&vres,  g_vres);
    cudaGetSymbolAddress((void**)&o,     g_o);
    cudaGetSymbolAddress((void**)&hbuf,  g_h);
    cudaGetSymbolAddress((void**)&hact,  g_hact);
    cudaGetSymbolAddress((void**)&mix,   g_mix);
    cudaGetSymbolAddress((void**)&w1pad, g_w1pad);
    cudaGetSymbolAddress((void**)&w2pad, g_w2pad);
    cudaGetSymbolAddress((void**)&wq,    g_wq);
    cudaGetSymbolAddress((void**)&wo,    g_wo);
    cudaGetSymbolAddress((void**)&wlog,  g_wlog);

    cudaFuncSetAttribute(gemm_tf32_kernel,
                         cudaFuncAttributeMaxDynamicSharedMemorySize, GEMM_SMEM);

    // L0
    embed_kernel<<<ROWS, 256>>>(tokens, tok_emb, pos_emb, x);
    // L1: pre-round the big logits weight once per launch
    roundcopy_kernel<<<(DIM * VOCAB / 4 + 255) / 256, 256>>>(w_logits, wlog,
                                                             DIM * VOCAB / 4);

    for (int d = 0; d < DEPTH; d++) {
        // weight preps first (L2, L3 on layer 0) so L5 = qkv GEMM for ncu
        roundcopy_kernel<<<(DIM * 3 * HD / 4 + 255) / 256, 256>>>(
            Wqkv + (size_t)d * DIM * 3 * HD, wq, DIM * 3 * HD / 4);
        roundcopy_kernel<<<(HD * DIM / 4 + 255) / 256, 256>>>(
            Wout + (size_t)d * HD * DIM, wo, HD * DIM / 4);
        // L4
        rmsnorm_kernel<<<ROWS, 128>>>(x, attn_norm_w + d * DIM, xn);
        // L5 (layer 0): the GEMM we want profiled
        launch_gemm(xn, wq, nullptr, nullptr, qkv, ROWS, 3 * HD, DIM);
        if (d > 0)
            vmix_kernel<<<ROWS, 128>>>(xn, vmix_w + (size_t)d * DIM * HEADS,
                                       vmix_b + d * HEADS, mix);
        {
            size_t n = (size_t)ROWS * HD;
            vprep_kernel<<<(unsigned)((n + 255) / 256), 256>>>(
                qkv, d > 0 ? mix : nullptr, vres, v, d == 0 ? vres : nullptr);
        }
        {
            size_t n = (size_t)ROWS * 2 * HEADS * 32;
            rope_kernel<<<(unsigned)((n + 255) / 256), 256>>>(qkv);
        }
        attn_kernel<<<dim3(4, NSEG, BATCH * HEADS), 128>>>(
            qkv, v, persist_mem + (size_t)d * 2 * HEADS * PMEM * DH, o);
        launch_gemm(o, wo, nullptr, x, x, ROWS, DIM, HD);
        rmsnorm_kernel<<<ROWS, 128>>>(x, ff_norm_w + d * DIM, xn);
        padw1_kernel<<<(DIM * FF2P + 255) / 256, 256>>>(
            ff_w1 + (size_t)d * DIM * FF2, w1pad);
        launch_gemm(xn, w1pad, nullptr, nullptr, hbuf, ROWS, FF2P, DIM);
        {
            size_t n = (size_t)ROWS * FFIP;
            geglu_kernel<<<(unsigned)((n + 255) / 256), 256>>>(
                hbuf, ff_b1 + (size_t)d * FF2, hact);
        }
        padw2_kernel<<<(FFIP * DIM + 255) / 256, 256>>>(
            ff_w2 + (size_t)d * FFI * DIM, w2pad);
        launch_gemm(hact, w2pad, ff_b2 + (size_t)d * DIM, x, x,
                    ROWS, DIM, FFIP);
    }

    rmsnorm_kernel<<<ROWS, 128>>>(x, final_norm_w, xn);
    launch_gemm(xn, wlog, nullptr, nullptr, out, ROWS, VOCAB, DIM);
}

// round 9
// speedup vs baseline: 1.7096x; 1.0830x over previous
#include <cuda_runtime.h>
#include <cuda_bf16.h>
#include <math.h>

// ---------------- problem constants ----------------
#define DEPTH   2
#define DIM     512
#define HEADS   8
#define DH      64
#define SEGLEN  512
#define PMEM    4
#define VOCAB   32000
#define BATCH   2
#define SEQ     4096
#define HD      512            // HEADS*DH
#define FFI     1365           // FF_INNER
#define FF2     2730           // 2*FF_INNER
#define FF2P    2816           // FF2 padded; interleaved (a,g) pairs
#define KFF2    1408           // FF2P/2: hact width = ff2 K dim (mult of 32)
#define ROWS    (BATCH*SEQ)    // 8192
#define NSEG    (SEQ/SEGLEN)   // 8

// ---------------- scratch (no cudaMalloc allowed) ----------------
__device__ __align__(16) float g_x    [ROWS*DIM];
__device__ __align__(16) float g_xn   [ROWS*DIM];
__device__ __align__(16) float g_qkv  [ROWS*3*HD];
__device__ __align__(16) float g_v    [ROWS*HD];
__device__ __align__(16) float g_vres [ROWS*HD];
__device__ __align__(16) float g_o    [ROWS*HD];
__device__ __align__(16) float g_hact [(size_t)ROWS*KFF2];
__device__ __align__(16) float g_mix  [ROWS*HEADS];
__device__ __align__(16) float g_w1pad[DIM*FF2P];
__device__ __align__(16) float g_b1i  [FF2P];
__device__ __align__(16) float g_w2pad[KFF2*DIM];
__device__ __align__(16) float g_wq   [DIM*3*HD];
__device__ __align__(16) float g_wo   [HD*DIM];
__device__ __align__(16) float g_wlog [DIM*VOCAB];

// ---------------- tf32 / f32x2 helpers ----------------
__device__ __forceinline__ float f2tf32(float x) {
    unsigned r;
    asm("cvt.rna.tf32.f32 %0, %1;" : "=r"(r) : "f"(x));
    return __uint_as_float(r);
}

typedef unsigned long long u64;
__device__ __forceinline__ u64 pack2(float lo, float hi) {
    u64 r; asm("mov.b64 %0, {%1, %2};" : "=l"(r) : "f"(lo), "f"(hi)); return r;
}
__device__ __forceinline__ void unpack2(u64 v, float& lo, float& hi) {
    asm("mov.b64 {%0, %1}, %2;" : "=f"(lo), "=f"(hi) : "l"(v));
}
__device__ __forceinline__ u64 fma2(u64 a, u64 b, u64 c) {
    u64 d; asm("fma.rn.f32x2 %0, %1, %2, %3;" : "=l"(d) : "l"(a), "l"(b), "l"(c));
    return d;
}
__device__ __forceinline__ u64 mul2(u64 a, u64 b) {
    u64 d; asm("mul.rn.f32x2 %0, %1, %2;" : "=l"(d) : "l"(a), "l"(b));
    return d;
}
__device__ __forceinline__ u64 add2(u64 a, u64 b) {
    u64 d; asm("add.rn.f32x2 %0, %1, %2;" : "=l"(d) : "l"(a), "l"(b));
    return d;
}

__device__ __forceinline__ void mma8(float* d, const float* a, const float* b) {
    asm volatile(
        "mma.sync.aligned.m16n8k8.row.col.f32.tf32.tf32.f32 "
        "{%0,%1,%2,%3},{%4,%5,%6,%7},{%8,%9},{%0,%1,%2,%3};"
        : "+f"(d[0]), "+f"(d[1]), "+f"(d[2]), "+f"(d[3])
        : "r"(__float_as_uint(a[0])), "r"(__float_as_uint(a[1])),
          "r"(__float_as_uint(a[2])), "r"(__float_as_uint(a[3])),
          "r"(__float_as_uint(b[0])), "r"(__float_as_uint(b[1])));
}

// ---------------- TF32 tensor-core GEMM, cp.async 3-stage (R8 config) ------
// C[M,N] = A[M,K] @ B[K,N]; epilogues:
//   GEGLU=false: (+bias)(+add) -> C[M,N]
//   GEGLU=true : (a,g) interleaved pairs -> C[M,N/2] = tf32((a+ba)*silu(g+bg))
// Requirements: M % 128 == 0, N % 128 == 0, K % 32 == 0, operands tf32-rounded.
#define AS_ST 36
#define BS_ST 136
#define A_STAGE (128*AS_ST)
#define B_STAGE (32*BS_ST)
#define STAGEF  (A_STAGE + B_STAGE)
#define GEMM_SMEM (3*STAGEF*4)       // 107520 bytes

__device__ __forceinline__ void cpasync16(float* dst_smem, const float* src) {
    unsigned d = (unsigned)__cvta_generic_to_shared(dst_smem);
    asm volatile("cp.async.cg.shared.global [%0], [%1], 16;\n"
                 :: "r"(d), "l"(src));
}

template <bool GEGLU>
__global__ void __launch_bounds__(256, 2)
gemm_tf32_kernel(const float* __restrict__ A, const float* __restrict__ B,
                 const float* __restrict__ bias, const float* __restrict__ add,
                 float* __restrict__ C, int M, int N, int K) {
    extern __shared__ float sm[];
    const int tid  = threadIdx.x;
    const int bm   = blockIdx.y * 128;
    const int bn   = blockIdx.x * 128;

    const int lane = tid & 31;
    const int g    = lane >> 2;
    const int tg   = lane & 3;
    const int wid  = tid >> 5;
    const int wm   = (wid & 3) * 32;
    const int wn   = (wid >> 2) * 64;

    float acc[2][8][4];
    #pragma unroll
    for (int mt = 0; mt < 2; mt++)
        #pragma unroll
        for (int nt = 0; nt < 8; nt++)
            #pragma unroll
            for (int c = 0; c < 4; c++) acc[mt][nt][c] = 0.f;

    const int ntile = K >> 5;

    #define STAGE(t, s) do {                                                  \
        float* as_ = sm + (s) * STAGEF;                                       \
        float* bs_ = as_ + A_STAGE;                                           \
        _Pragma("unroll")                                                     \
        for (int i_ = 0; i_ < 4; i_++) {                                      \
            int lin = tid + i_ * 256;                                         \
            int r = lin >> 3, c = (lin & 7) * 4;                              \
            cpasync16(as_ + r * AS_ST + c,                                    \
                      A + (size_t)(bm + r) * K + (t) * 32 + c);               \
        }                                                                     \
        _Pragma("unroll")                                                     \
        for (int i_ = 0; i_ < 4; i_++) {                                      \
            int lin = tid + i_ * 256;                                         \
            int r = lin >> 5, c = (lin & 31) * 4;                             \
            cpasync16(bs_ + r * BS_ST + c,                                    \
                      B + (size_t)((t) * 32 + r) * N + bn + c);               \
        }                                                                     \
        asm volatile("cp.async.commit_group;\n" ::: "memory");                \
    } while (0)

    STAGE(0, 0);
    if (ntile > 1) STAGE(1, 1);
    asm volatile("cp.async.wait_group 1;\n" ::: "memory");
    __syncthreads();

    for (int t = 0; t < ntile; t++) {
        const int s = t % 3;
        if (t + 2 < ntile) STAGE(t + 2, (t + 2) % 3);

        const float* as_ = sm + s * STAGEF;
        const float* bs_ = as_ + A_STAGE;

        #pragma unroll
        for (int ks = 0; ks < 4; ks++) {
            int k0 = ks * 8;
            float af[2][4];
            #pragma unroll
            for (int mt = 0; mt < 2; mt++) {
                int m = wm + mt * 16;
                af[mt][0] = as_[(m + g    ) * AS_ST + k0 + tg    ];
                af[mt][1] = as_[(m + g + 8) * AS_ST + k0 + tg    ];
                af[mt][2] = as_[(m + g    ) * AS_ST + k0 + tg + 4];
                af[mt][3] = as_[(m + g + 8) * AS_ST + k0 + tg + 4];
            }
            float bf[8][2];
            #pragma unroll
            for (int nt = 0; nt < 8; nt++) {
                bf[nt][0] = bs_[(k0 + tg    ) * BS_ST + wn + nt * 8 + g];
                bf[nt][1] = bs_[(k0 + tg + 4) * BS_ST + wn + nt * 8 + g];
            }
            #pragma unroll
            for (int mt = 0; mt < 2; mt++)
                #pragma unroll
                for (int nt = 0; nt < 8; nt++)
                    mma8(acc[mt][nt], af[mt], bf[nt]);
        }

        if (t + 2 < ntile)
            asm volatile("cp.async.wait_group 1;\n" ::: "memory");
        else
            asm volatile("cp.async.wait_group 0;\n" ::: "memory");
        __syncthreads();
    }

    // epilogue
    #pragma unroll
    for (int mt = 0; mt < 2; mt++) {
        #pragma unroll
        for (int nt = 0; nt < 8; nt++) {
            int r0 = bm + wm + mt * 16 + g;
            int c0 = bn + wn + nt * 8 + tg * 2;
            #pragma unroll
            for (int half = 0; half < 2; half++) {
                int r = r0 + half * 8;
                float v0 = acc[mt][nt][half * 2 + 0];
                float v1 = acc[mt][nt][half * 2 + 1];
                if (GEGLU) {
                    // c0 even; (v0,v1) = (a_i, g_i), i = c0/2
                    float a  = v0 + bias[c0];
                    float gg = v1 + bias[c0 + 1];
                    float sig = 1.f / (1.f + expf(-gg));
                    C[(size_t)r * (N >> 1) + (c0 >> 1)] = f2tf32(a * gg * sig);
                } else {
                    if (bias) { v0 += bias[c0]; v1 += bias[c0 + 1]; }
                    if (add)  { v0 += add[(size_t)r * N + c0];
                                v1 += add[(size_t)r * N + c0 + 1]; }
                    C[(size_t)r * N + c0]     = v0;
                    C[(size_t)r * N + c0 + 1] = v1;
                }
            }
        }
    }
}

static inline void launch_gemm(const float* A, const float* B, const float* bias,
                               const float* add, float* C, int M, int N, int K) {
    dim3 grid(N / 128, M / 128);
    gemm_tf32_kernel<false><<<grid, 256, GEMM_SMEM>>>(A, B, bias, add, C, M, N, K);
}
static inline void launch_gemm_geglu(const float* A, const float* B,
                                     const float* bias, float* C,
                                     int M, int N, int K) {
    dim3 grid(N / 128, M / 128);
    gemm_tf32_kernel<true><<<grid, 256, GEMM_SMEM>>>(A, B, bias, nullptr, C, M, N, K);
}

// ---------------- rna round-copy (for weight B operands) ----------------
__global__ void roundcopy_kernel(const float* __restrict__ in,
                                 float* __restrict__ out, int n4) {
    int i = blockIdx.x * blockDim.x + threadIdx.x;
    if (i >= n4) return;
    float4 v = ((const float4*)in)[i];
    ((float4*)out)[i] = make_float4(f2tf32(v.x), f2tf32(v.y),
                                    f2tf32(v.z), f2tf32(v.w));
}

// ---------------- embedding ----------------
__global__ void embed_kernel(const int* __restrict__ tokens,
                             const float* __restrict__ tok_emb,
                             const float* __restrict__ pos_emb,
                             float* __restrict__ x) {
    int row = blockIdx.x;
    int s = row % SEQ;
    int tok = tokens[row];
    const float* te = tok_emb + (size_t)tok * DIM;
    const float* pe = pos_emb + (size_t)s * DIM;
    float* xr = x + (size_t)row * DIM;
    for (int c = threadIdx.x; c < DIM; c += blockDim.x)
        xr[c] = te[c] + pe[c];
}

// ---------------- rmsnorm (tf32-rounded output: GEMM A operand) ------------
__global__ void rmsnorm_kernel(const float* __restrict__ in,
                               const float* __restrict__ w,
                               float* __restrict__ out) {
    int row = blockIdx.x;
    const float* xr = in + (size_t)row * DIM;
    float* orow = out + (size_t)row * DIM;
    int tid = threadIdx.x; // 128
    float acc = 0.f;
    float v[4];
    #pragma unroll
    for (int i = 0; i < 4; i++) {
        v[i] = xr[tid + i * 128];
        acc += v[i] * v[i];
    }
    for (int off = 16; off; off >>= 1) acc += __shfl_down_sync(~0u, acc, off);
    __shared__ float sh[4];
    int lane = tid & 31, wp = tid >> 5;
    if (lane == 0) sh[wp] = acc;
    __syncthreads();
    __shared__ float s_scale;
    if (tid == 0) {
        float ss = (sh[0] + sh[1] + sh[2] + sh[3]) / (float)DIM;
        s_scale = rsqrtf(ss + 1e-6f);
    }
    __syncthreads();
    float sc = s_scale;
    #pragma unroll
    for (int i = 0; i < 4; i++) {
        int c = tid + i * 128;
        orow[c] = f2tf32(v[i] * sc * w[c]);
    }
}

// ---------------- vmix ----------------
__global__ void vmix_kernel(const float* __restrict__ xn,
                            const float* __restrict__ w,   // [512,8]
                            const float* __restrict__ b,   // [8]
                            float* __restrict__ mix) {
    int row = blockIdx.x, tid = threadIdx.x; // 128
    float acc[8] = {0,0,0,0,0,0,0,0};
    const float* xr = xn + (size_t)row * DIM;
    for (int k = tid; k < DIM; k += 128) {
        float xv = xr[k];
        const float* wr = w + k * HEADS;
        #pragma unroll
        for (int h = 0; h < 8; h++) acc[h] += xv * wr[h];
    }
    __shared__ float sh[4][8];
    int lane = tid & 31, wp = tid >> 5;
    #pragma unroll
    for (int h = 0; h < 8; h++) {
        float v = acc[h];
        for (int off = 16; off; off >>= 1) v += __shfl_down_sync(~0u, v, off);
        if (lane == 0) sh[wp][h] = v;
    }
    __syncthreads();
    if (tid < 8) {
        float v = sh[0][tid] + sh[1][tid] + sh[2][tid] + sh[3][tid] + b[tid];
        mix[(size_t)row * HEADS + tid] = 1.f / (1.f + expf(-v));
    }
}

// ---------------- v preparation ----------------
__global__ void vprep_kernel(const float* __restrict__ qkv,
                             const float* __restrict__ mix,
                             const float* __restrict__ vres,
                             float* __restrict__ vout,
                             float* __restrict__ vres_out) {
    size_t idx = (size_t)blockIdx.x * blockDim.x + threadIdx.x;
    if (idx >= (size_t)ROWS * HD) return;
    size_t row = idx >> 9;
    int col = (int)(idx & 511);
    int h = col >> 6;
    float v = qkv[row * (3 * HD) + 2 * HD + col];
    if (vres_out) vres_out[idx] = v;
    if (mix) {
        float mx = mix[row * HEADS + h];
        v = v + (vres[idx] - v) * mx;
    }
    vout[idx] = v;
}

// ---------------- rope ----------------
__global__ void rope_kernel(float* __restrict__ qkv) {
    size_t idx = (size_t)blockIdx.x * blockDim.x + threadIdx.x;
    if (idx >= (size_t)ROWS * 2 * HEADS * 32) return;
    int i  = (int)(idx & 31);
    int h  = (int)((idx >> 5) & 7);
    int qk = (int)((idx >> 8) & 1);
    size_t row = idx >> 9;
    int s = (int)(row % SEQ);
    float inv = exp2f(-(float)i * 0.41524103f);   // 10000^(-2i/64)
    float f = (float)s * inv;
    float cs, sn;
    sincosf(f, &sn, &cs);
    size_t base = row * (3 * HD) + (size_t)qk * HD + h * DH + 2 * i;
    float x1 = qkv[base], x2 = qkv[base + 1];
    qkv[base]     = x1 * cs - x2 * sn;
    qkv[base + 1] = x1 * sn + x2 * cs;
}

// ---------------- attention (packed f32x2 FFMA; tf32-rounded output) -------
__global__ void __launch_bounds__(128)
attn_kernel(const float* __restrict__ qkv,
            const float* __restrict__ vmem,
            const float* __restrict__ pmem,
            float* __restrict__ out) {
    const int qb = blockIdx.x, w = blockIdx.y;
    const int b = blockIdx.z / HEADS, h = blockIdx.z % HEADS;
    const int tid = threadIdx.x;
    const int qi = qb * 128 + tid;
    const int s = w * SEGLEN + qi;
    const size_t row = (size_t)(b * SEQ + s);

    u64 q2[32];
    {
        const float* qp = qkv + row * (3 * HD) + h * DH;
        #pragma unroll
        for (int c = 0; c < 32; c++)
            q2[c] = pack2(qp[2 * c] * 0.125f, qp[2 * c + 1] * 0.125f);
    }
    u64 o2[32];
    #pragma unroll
    for (int c = 0; c < 32; c++) o2[c] = 0ull;   // (0.0f, 0.0f)
    float m = -INFINITY, l = 0.f;

    __shared__ __align__(8) float ks[32][64];
    __shared__ __align__(8) float vs[32][64];

    const int jmax = qi + PMEM;
    const int qi_last = qb * 128 + 127;
    const int nch = (qi_last + PMEM) / 32 + 1;

    for (int ch = 0; ch < nch; ch++) {
        const int j0 = ch * 32;
        for (int e = tid; e < 32 * 64; e += 128) {
            int jj = e >> 6, c = e & 63;
            int j = j0 + jj;
            float kv = 0.f, vv = 0.f;
            if (j < PMEM) {
                kv = pmem[(0 * HEADS + h) * PMEM * DH + j * DH + c];
                vv = pmem[(1 * HEADS + h) * PMEM * DH + j * DH + c];
            } else if (j - PMEM < SEGLEN) {
                int sk = w * SEGLEN + (j - PMEM);
                size_t rk = (size_t)(b * SEQ + sk);
                kv = qkv[rk * (3 * HD) + HD + h * DH + c];
                vv = vmem[rk * HD + h * DH + c];
            }
            ks[jj][c] = kv;
            vs[jj][c] = vv;
        }
        __syncthreads();

        if (j0 <= jmax) {
            float sc[32];
            float cmax = -INFINITY;
            #pragma unroll
            for (int jj = 0; jj < 32; jj++) {
                const u64* k2 = (const u64*)&ks[jj][0];
                u64 a0 = 0ull, a1 = 0ull, a2 = 0ull, a3 = 0ull;
                #pragma unroll
                for (int c = 0; c < 32; c += 4) {
                    a0 = fma2(q2[c    ], k2[c    ], a0);
                    a1 = fma2(q2[c + 1], k2[c + 1], a1);
                    a2 = fma2(q2[c + 2], k2[c + 2], a2);
                    a3 = fma2(q2[c + 3], k2[c + 3], a3);
                }
                u64 t = add2(add2(a0, a1), add2(a2, a3));
                float lo, hi;
                unpack2(t, lo, hi);
                float acc = lo + hi;
                sc[jj] = (j0 + jj <= jmax) ? acc : -INFINITY;
                cmax = fmaxf(cmax, sc[jj]);
            }
            float mnew = fmaxf(m, cmax);
            float f = __expf(m - mnew);
            l *= f;
            u64 fpack = pack2(f, f);
            #pragma unroll
            for (int c = 0; c < 32; c++) o2[c] = mul2(o2[c], fpack);
            #pragma unroll
            for (int jj = 0; jj < 32; jj++) {
                float p = __expf(sc[jj] - mnew);
                l += p;
                u64 pp = pack2(p, p);
                const u64* v2 = (const u64*)&vs[jj][0];
                #pragma unroll
                for (int c = 0; c < 32; c++)
                    o2[c] = fma2(pp, v2[c], o2[c]);
            }
            m = mnew;
        }
        __syncthreads();
    }

    float invl = 1.f / l;
    float* op = out + row * HD + h * DH;
    #pragma unroll
    for (int c = 0; c < 32; c++) {
        float lo, hi;
        unpack2(o2[c], lo, hi);
        op[2 * c]     = f2tf32(lo * invl);
        op[2 * c + 1] = f2tf32(hi * invl);
    }
}

// ---------------- ff_w1 interleave+pad+round: [DIM,FF2] -> [DIM,FF2P] ------
// col 2i = a_i = w1[:, i], col 2i+1 = g_i = w1[:, FFI+i], zero for i >= FFI
__global__ void padw1_kernel(const float* __restrict__ w,
                             float* __restrict__ out) {
    int idx = blockIdx.x * blockDim.x + threadIdx.x;
    if (idx >= DIM * KFF2) return;
    int r = idx / KFF2, i = idx - r * KFF2;
    float a = 0.f, gg = 0.f;
    if (i < FFI) {
        a  = f2tf32(w[(size_t)r * FF2 + i]);
        gg = f2tf32(w[(size_t)r * FF2 + FFI + i]);
    }
    out[(size_t)r * FF2P + 2 * i]     = a;
    out[(size_t)r * FF2P + 2 * i + 1] = gg;
}

// ---------------- ff_b1 interleave: [FF2] -> [FF2P] ----------------
__global__ void padb1_kernel(const float* __restrict__ b1,
                             float* __restrict__ out) {
    int i = blockIdx.x * blockDim.x + threadIdx.x;
    if (i >= KFF2) return;
    out[2 * i]     = (i < FFI) ? b1[i] : 0.f;
    out[2 * i + 1] = (i < FFI) ? b1[FFI + i] : 0.f;
}

// ---------------- ff_w2 pad+round: [FFI, DIM] -> [KFF2, DIM] ----------------
__global__ void padw2_kernel(const float* __restrict__ w,
                             float* __restrict__ out) {
    int idx = blockIdx.x * blockDim.x + threadIdx.x;
    if (idx >= KFF2 * DIM) return;
    int k = idx / DIM;
    out[idx] = (k < FFI) ? f2tf32(w[idx]) : 0.f;
}

// ---------------- launch ----------------
extern "C" void kernel_launch(void* const* d_in, const int* in_sizes, int n_in,
                              void* d_out, int out_size) {
    const int*   tokens       = (const int*)  d_in[0];
    const float* tok_emb      = (const float*)d_in[1];
    const float* pos_emb      = (const float*)d_in[2];
    const float* attn_norm_w  = (const float*)d_in[3];
    const float* Wqkv         = (const float*)d_in[4];
    const float* persist_mem  = (const float*)d_in[5];
    const float* Wout         = (const float*)d_in[6];
    const float* vmix_w       = (const float*)d_in[7];
    const float* vmix_b       = (const float*)d_in[8];
    const float* ff_norm_w    = (const float*)d_in[9];
    const float* ff_w1        = (const float*)d_in[10];
    const float* ff_b1        = (const float*)d_in[11];
    const float* ff_w2        = (const float*)d_in[12];
    const float* ff_b2        = (const float*)d_in[13];
    const float* final_norm_w = (const float*)d_in[14];
    const float* w_logits     = (const float*)d_in[15];
    float* out = (float*)d_out;

    float *x, *xn, *qkv, *v, *vres, *o, *hact, *mix;
    float *w1pad, *b1i, *w2pad, *wq, *wo, *wlog;
    cudaGetSymbolAddress((void**)&x,     g_x);
    cudaGetSymbolAddress((void**)&xn,    g_xn);
    cudaGetSymbolAddress((void**)&qkv,   g_qkv);
    cudaGetSymbolAddress((void**)&v,     g_v);
    cudaGetSymbolAddress((void**)&vres,  g_vres);
    cudaGetSymbolAddress((void**)&o,     g_o);
    cudaGetSymbolAddress((void**)&hact,  g_hact);
    cudaGetSymbolAddress((void**)&mix,   g_mix);
    cudaGetSymbolAddress((void**)&w1pad, g_w1pad);
    cudaGetSymbolAddress((void**)&b1i,   g_b1i);
    cudaGetSymbolAddress((void**)&w2pad, g_w2pad);
    cudaGetSymbolAddress((void**)&wq,    g_wq);
    cudaGetSymbolAddress((void**)&wo,    g_wo);
    cudaGetSymbolAddress((void**)&wlog,  g_wlog);

    cudaFuncSetAttribute(gemm_tf32_kernel<false>,
                         cudaFuncAttributeMaxDynamicSharedMemorySize, GEMM_SMEM);
    cudaFuncSetAttribute(gemm_tf32_kernel<true>,
                         cudaFuncAttributeMaxDynamicSharedMemorySize, GEMM_SMEM);

    embed_kernel<<<ROWS, 256>>>(tokens, tok_emb, pos_emb, x);
    roundcopy_kernel<<<(DIM * VOCAB / 4 + 255) / 256, 256>>>(w_logits, wlog,
                                                             DIM * VOCAB / 4);

    for (int d = 0; d < DEPTH; d++) {
        roundcopy_kernel<<<(DIM * 3 * HD / 4 + 255) / 256, 256>>>(
            Wqkv + (size_t)d * DIM * 3 * HD, wq, DIM * 3 * HD / 4);
        roundcopy_kernel<<<(HD * DIM / 4 + 255) / 256, 256>>>(
            Wout + (size_t)d * HD * DIM, wo, HD * DIM / 4);
        rmsnorm_kernel<<<ROWS, 128>>>(x, attn_norm_w + d * DIM, xn);
        launch_gemm(xn, wq, nullptr, nullptr, qkv, ROWS, 3 * HD, DIM);
        if (d > 0)
            vmix_kernel<<<ROWS, 128>>>(xn, vmix_w + (size_t)d * DIM * HEADS,
                                       vmix_b + d * HEADS, mix);
        {
            size_t n = (size_t)ROWS * HD;
            vprep_kernel<<<(unsigned)((n + 255) / 256), 256>>>(
                qkv, d > 0 ? mix : nullptr, vres, v, d == 0 ? vres : nullptr);
        }
        {
            size_t n = (size_t)ROWS * 2 * HEADS * 32;
            rope_kernel<<<(unsigned)((n + 255) / 256), 256>>>(qkv);
        }
        attn_kernel<<<dim3(4, NSEG, BATCH * HEADS), 128>>>(
            qkv, v, persist_mem + (size_t)d * 2 * HEADS * PMEM * DH, o);
        launch_gemm(o, wo, nullptr, x, x, ROWS, DIM, HD);
        rmsnorm_kernel<<<ROWS, 128>>>(x, ff_norm_w + d * DIM, xn);
        padw1_kernel<<<(DIM * KFF2 + 255) / 256, 256>>>(
            ff_w1 + (size_t)d * DIM * FF2, w1pad);
        padb1_kernel<<<(KFF2 + 255) / 256, 256>>>(
            ff_b1 + (size_t)d * FF2, b1i);
        // ff1 GEMM with fused GEGLU epilogue -> hact [ROWS, KFF2]
        launch_gemm_geglu(xn, w1pad, b1i, hact, ROWS, FF2P, DIM);
        padw2_kernel<<<(KFF2 * DIM + 255) / 256, 256>>>(
            ff_w2 + (size_t)d * FFI * DIM, w2pad);
        launch_gemm(hact, w2pad, ff_b2 + (size_t)d * DIM, x, x,
                    ROWS, DIM, KFF2);
    }

    rmsnorm_kernel<<<ROWS, 128>>>(x, final_norm_w, xn);
    launch_gemm(xn, wlog, nullptr, nullptr, out, ROWS, VOCAB, DIM);
}